// round 1
// baseline (speedup 1.0000x reference)
#include <cuda_runtime.h>
#include <math.h>

// Problem shape (fixed by reference setup_inputs)
#define BATCH 16
#define CHAN  3
#define HDIM  512
#define WDIM  512
#define RSTRIP 64                    // output rows per block
#define STRIPS (HDIM / RSTRIP)       // 8
#define NBLOCKS (BATCH * STRIPS)     // 128
#define EPSV 1e-6f

__device__ float g_partials[NBLOCKS];

__global__ __launch_bounds__(WDIM) void charbonnier_strip_kernel(
    const float* __restrict__ x, const float* __restrict__ y)
{
    __shared__ float hs[7][WDIM];        // ring buffer: horizontal 7-tap box sums
    __shared__ float drow[WDIM + 6];     // channel-summed diff row, zero-padded +-3
    __shared__ float warpsum[16];

    const int blk = blockIdx.x;
    const int b   = blk / STRIPS;
    const int s   = blk % STRIPS;
    const int h0  = s * RSTRIP;
    const int w   = threadIdx.x;

    // zero the horizontal halo once (never overwritten)
    if (w < 3) { drow[w] = 0.0f; drow[WDIM + 3 + w] = 0.0f; }

    const size_t plane = (size_t)HDIM * WDIM;
    const float* xb = x + (size_t)b * CHAN * plane;
    const float* yb = y + (size_t)b * CHAN * plane;

    float acc = 0.0f;

    // stream rows h0-3 .. h0+RSTRIP+2  (RSTRIP+6 rows)
    #pragma unroll 1
    for (int idx = 0; idx < RSTRIP + 6; ++idx) {
        const int r = h0 - 3 + idx;

        float d = 0.0f;
        if (r >= 0 && r < HDIM) {
            const size_t off = (size_t)r * WDIM + w;
            d = (xb[off]              - yb[off])
              + (xb[plane + off]      - yb[plane + off])
              + (xb[2 * plane + off]  - yb[2 * plane + off]);
        }
        drow[w + 3] = d;
        __syncthreads();   // drow ready for all; also protects hs ring reuse

        // horizontal 7-tap box sum
        const float hsv = drow[w]     + drow[w + 1] + drow[w + 2] + drow[w + 3]
                        + drow[w + 4] + drow[w + 5] + drow[w + 6];
        hs[idx % 7][w] = hsv;
        __syncthreads();   // hs row ready; also protects drow before next write

        if (idx >= 6) {
            // the 7 most recent hsum rows occupy all 7 ring slots
            const float vs = hs[0][w] + hs[1][w] + hs[2][w] + hs[3][w]
                           + hs[4][w] + hs[5][w] + hs[6][w];
            const float v = vs * (1.0f / 49.0f);
            acc += sqrtf(v * v + EPSV);
        }
    }

    // block reduction (deterministic)
    #pragma unroll
    for (int o = 16; o; o >>= 1) acc += __shfl_xor_sync(0xffffffffu, acc, o);
    const int lane = w & 31, wid = w >> 5;
    if (lane == 0) warpsum[wid] = acc;
    __syncthreads();
    if (wid == 0) {
        float v = (lane < 16) ? warpsum[lane] : 0.0f;
        #pragma unroll
        for (int o = 8; o; o >>= 1) v += __shfl_xor_sync(0xffffffffu, v, o);
        if (lane == 0) g_partials[blk] = v;
    }
}

__global__ void charbonnier_reduce_kernel(float* __restrict__ out)
{
    __shared__ float ws[4];
    const int t = threadIdx.x;             // 128 threads
    float v = g_partials[t];
    #pragma unroll
    for (int o = 16; o; o >>= 1) v += __shfl_xor_sync(0xffffffffu, v, o);
    if ((t & 31) == 0) ws[t >> 5] = v;
    __syncthreads();
    if (t == 0) {
        const float total = ws[0] + ws[1] + ws[2] + ws[3];
        out[0] = total / (float)((size_t)BATCH * HDIM * WDIM);
    }
}

extern "C" void kernel_launch(void* const* d_in, const int* in_sizes, int n_in,
                              void* d_out, int out_size)
{
    (void)in_sizes; (void)n_in; (void)out_size;
    const float* x = (const float*)d_in[0];
    const float* y = (const float*)d_in[1];
    float* out = (float*)d_out;

    charbonnier_strip_kernel<<<NBLOCKS, WDIM>>>(x, y);
    charbonnier_reduce_kernel<<<1, 128>>>(out);
}

// round 2
// speedup vs baseline: 2.7569x; 2.7569x over previous
#include <cuda_runtime.h>
#include <math.h>

// Shape fixed by reference: x,y = [16, 3, 512, 512] f32
#define BATCH   16
#define HDIM    512
#define WDIM    512
#define RSTRIP  64                    // output rows per block
#define STRIPS  (HDIM / RSTRIP)       // 8
#define NBLOCKS (BATCH * STRIPS)      // 128
#define ROWSIN  (RSTRIP + 6)          // 70 input rows incl. halo
#define CHUNKS  ((ROWSIN + 3) / 4)    // 18 (4 rows per chunk)
#define EPSV    1e-6f

__device__ float        g_partials[NBLOCKS];
__device__ unsigned int g_count;     // zero-init at load; reset by last block

__device__ __forceinline__ void rg_barrier(int rg) {
    // 128-thread named barrier per row-group (ids 1..4)
    asm volatile("bar.sync %0, %1;" :: "r"(rg + 1), "r"(128) : "memory");
}

__global__ __launch_bounds__(512) void charb_kernel(
    const float* __restrict__ x, const float* __restrict__ y,
    float* __restrict__ out)
{
    __shared__ float drow[4][520];     // per-row-group diff row, halo-padded (d[c] at [4+c])
    __shared__ float hs[16][WDIM];     // ring of horizontal 7-tap sums
    __shared__ float warpsum[16];
    __shared__ bool  isLast;

    const int tid  = threadIdx.x;
    const int rg   = tid >> 7;         // row-group 0..3
    const int c4   = tid & 127;        // float4 column index
    const int col0 = c4 << 2;

    const int blk = blockIdx.x;
    const int b   = blk / STRIPS;
    const int s   = blk % STRIPS;
    const int h0  = s * RSTRIP;

    if (c4 == 0) {                     // zero side halos (incl. f[0]/f[11] pads)
        drow[rg][0] = drow[rg][1] = drow[rg][2] = drow[rg][3] = 0.f;
        drow[rg][516] = drow[rg][517] = drow[rg][518] = drow[rg][519] = 0.f;
    }

    const size_t plane = (size_t)HDIM * WDIM;
    const float* xb = x + (size_t)b * 3 * plane;
    const float* yb = y + (size_t)b * 3 * plane;

    float4 a0, a1, a2, q0, q1, q2;     // pipelined raw loads (cur chunk)
    bool   valid;

    {   // prologue: load chunk 0 (input row idx = rg)
        const int r = h0 - 3 + rg;
        valid = (r >= 0) && (r < HDIM);
        if (valid) {
            const float* xp = xb + (size_t)r * WDIM + col0;
            const float* yp = yb + (size_t)r * WDIM + col0;
            a0 = *(const float4*)(xp);
            a1 = *(const float4*)(xp + plane);
            a2 = *(const float4*)(xp + 2 * plane);
            q0 = *(const float4*)(yp);
            q1 = *(const float4*)(yp + plane);
            q2 = *(const float4*)(yp + 2 * plane);
        }
    }

    float acc = 0.f;

    #pragma unroll 1
    for (int ch = 0; ch < CHUNKS; ++ch) {
        const int idx = ch * 4 + rg;   // global input-row index within strip stream

        // channel-summed diff for current chunk -> smem
        float4 d = make_float4(0.f, 0.f, 0.f, 0.f);
        if (valid) {
            d.x = (a0.x - q0.x) + (a1.x - q1.x) + (a2.x - q2.x);
            d.y = (a0.y - q0.y) + (a1.y - q1.y) + (a2.y - q2.y);
            d.z = (a0.z - q0.z) + (a1.z - q1.z) + (a2.z - q2.z);
            d.w = (a0.w - q0.w) + (a1.w - q1.w) + (a2.w - q2.w);
        }
        *(float4*)&drow[rg][4 + col0] = d;

        // prefetch next chunk (latency hidden behind both smem phases)
        const int nidx = idx + 4;
        const int nr   = h0 - 3 + nidx;
        valid = (nidx < ROWSIN) && (nr >= 0) && (nr < HDIM);
        if (valid) {
            const float* xp = xb + (size_t)nr * WDIM + col0;
            const float* yp = yb + (size_t)nr * WDIM + col0;
            a0 = *(const float4*)(xp);
            a1 = *(const float4*)(xp + plane);
            a2 = *(const float4*)(xp + 2 * plane);
            q0 = *(const float4*)(yp);
            q1 = *(const float4*)(yp + plane);
            q2 = *(const float4*)(yp + 2 * plane);
        }

        rg_barrier(rg);                 // drow ready within this row-group

        // horizontal 7-tap sums for 4 columns via 3 aligned LDS.128
        float f[12];
        *(float4*)&f[0] = *(const float4*)&drow[rg][col0];
        *(float4*)&f[4] = *(const float4*)&drow[rg][col0 + 4];
        *(float4*)&f[8] = *(const float4*)&drow[rg][col0 + 8];
        const float s0 = ((f[1] + f[2]) + (f[3] + f[4])) + ((f[5] + f[6]) + f[7]);
        const float s1 = s0 - f[1] + f[8];
        const float s2 = s1 - f[2] + f[9];
        const float s3 = s2 - f[3] + f[10];
        *(float4*)&hs[idx & 15][col0] = make_float4(s0, s1, s2, s3);

        __syncthreads();                // hs rows from all row-groups visible
                                        // (ring WAR safe: writes ch+1 hit slots disjoint
                                        //  from reads of ch; 14 consecutive < 16)

        // vertical 7-tap + Charbonnier for output row o = idx - 6
        const int o = idx - 6;
        if (o >= 0 && o < RSTRIP) {
            float4 v = *(const float4*)&hs[o & 15][col0];
            #pragma unroll
            for (int t = 1; t < 7; ++t) {
                const float4 hv = *(const float4*)&hs[(o + t) & 15][col0];
                v.x += hv.x; v.y += hv.y; v.z += hv.z; v.w += hv.w;
            }
            const float inv = 1.f / 49.f;
            v.x *= inv; v.y *= inv; v.z *= inv; v.w *= inv;
            acc += (sqrtf(v.x * v.x + EPSV) + sqrtf(v.y * v.y + EPSV))
                 + (sqrtf(v.z * v.z + EPSV) + sqrtf(v.w * v.w + EPSV));
        }
    }

    // block reduction
    #pragma unroll
    for (int off = 16; off; off >>= 1) acc += __shfl_xor_sync(0xffffffffu, acc, off);
    if ((tid & 31) == 0) warpsum[tid >> 5] = acc;
    __syncthreads();
    if (tid < 32) {
        float v = (tid < 16) ? warpsum[tid] : 0.f;
        #pragma unroll
        for (int off = 8; off; off >>= 1) v += __shfl_xor_sync(0xffffffffu, v, off);
        if (tid == 0) {
            g_partials[blk] = v;
            __threadfence();
            const unsigned int t = atomicAdd(&g_count, 1u);
            isLast = (t == NBLOCKS - 1);
        }
    }
    __syncthreads();

    // last-arriving block folds partials -> scalar (deterministic order)
    if (isLast) {
        __threadfence();
        float v = (tid < NBLOCKS) ? g_partials[tid] : 0.f;
        #pragma unroll
        for (int off = 16; off; off >>= 1) v += __shfl_xor_sync(0xffffffffu, v, off);
        if ((tid & 31) == 0) warpsum[tid >> 5] = v;
        __syncthreads();
        if (tid < 32) {
            float v2 = (tid < 16) ? warpsum[tid] : 0.f;
            #pragma unroll
            for (int off = 8; off; off >>= 1) v2 += __shfl_xor_sync(0xffffffffu, v2, off);
            if (tid == 0) {
                out[0]  = v2 / (float)((size_t)BATCH * HDIM * WDIM);
                g_count = 0u;
            }
        }
    }
}

extern "C" void kernel_launch(void* const* d_in, const int* in_sizes, int n_in,
                              void* d_out, int out_size)
{
    (void)in_sizes; (void)n_in; (void)out_size;
    const float* x = (const float*)d_in[0];
    const float* y = (const float*)d_in[1];
    float* out = (float*)d_out;

    charb_kernel<<<NBLOCKS, 512>>>(x, y, out);
}

// round 3
// speedup vs baseline: 3.0595x; 1.1098x over previous
#include <cuda_runtime.h>
#include <math.h>

// Shape fixed by reference: x,y = [16, 3, 512, 512] f32
#define BATCH   16
#define HDIM    512
#define WDIM    512
#define RSTRIP  32                    // output rows per block
#define STRIPS  (HDIM / RSTRIP)       // 16
#define NBLOCKS (BATCH * STRIPS)      // 256
#define ROWSIN  (RSTRIP + 6)          // 38 input rows incl. halo
#define RGROUPS 2                     // row-groups per block
#define THREADS (RGROUPS * 128)       // 256
#define CHUNKS  ((ROWSIN + RGROUPS - 1) / RGROUPS)  // 19
#define EPSV    1e-6f

__device__ float        g_partials[NBLOCKS];
__device__ unsigned int g_count;     // zero-init at load; reset by last block

__device__ __forceinline__ void rg_barrier(int rg) {
    // 128-thread named barrier per row-group (ids 1..RGROUPS)
    asm volatile("bar.sync %0, %1;" :: "r"(rg + 1), "r"(128) : "memory");
}

__global__ __launch_bounds__(THREADS, 2) void charb_kernel(
    const float* __restrict__ x, const float* __restrict__ y,
    float* __restrict__ out)
{
    __shared__ float drow[RGROUPS][520]; // per-row-group diff row, halo-padded (d[c] at [4+c])
    __shared__ float hs[16][WDIM];       // ring of horizontal 7-tap sums
    __shared__ float warpsum[THREADS / 32];
    __shared__ bool  isLast;

    const int tid  = threadIdx.x;
    const int rg   = tid >> 7;         // row-group 0..RGROUPS-1
    const int c4   = tid & 127;        // float4 column index
    const int col0 = c4 << 2;

    const int blk = blockIdx.x;
    const int b   = blk / STRIPS;
    const int s   = blk % STRIPS;
    const int h0  = s * RSTRIP;

    if (c4 == 0) {                     // zero side halos (incl. f[0]/f[11] pads)
        drow[rg][0] = drow[rg][1] = drow[rg][2] = drow[rg][3] = 0.f;
        drow[rg][516] = drow[rg][517] = drow[rg][518] = drow[rg][519] = 0.f;
    }

    const size_t plane = (size_t)HDIM * WDIM;
    const float* xb = x + (size_t)b * 3 * plane;
    const float* yb = y + (size_t)b * 3 * plane;

    float4 a0, a1, a2, q0, q1, q2;     // pipelined raw loads (cur chunk)
    bool   valid;

    {   // prologue: load chunk 0 (input row idx = rg)
        const int r = h0 - 3 + rg;
        valid = (r >= 0) && (r < HDIM);
        if (valid) {
            const float* xp = xb + (size_t)r * WDIM + col0;
            const float* yp = yb + (size_t)r * WDIM + col0;
            a0 = *(const float4*)(xp);
            a1 = *(const float4*)(xp + plane);
            a2 = *(const float4*)(xp + 2 * plane);
            q0 = *(const float4*)(yp);
            q1 = *(const float4*)(yp + plane);
            q2 = *(const float4*)(yp + 2 * plane);
        }
    }

    float acc = 0.f;

    #pragma unroll 1
    for (int ch = 0; ch < CHUNKS; ++ch) {
        const int idx = ch * RGROUPS + rg;  // input-row index within strip stream

        // channel-summed diff for current chunk -> smem
        float4 d = make_float4(0.f, 0.f, 0.f, 0.f);
        if (valid) {
            d.x = (a0.x - q0.x) + (a1.x - q1.x) + (a2.x - q2.x);
            d.y = (a0.y - q0.y) + (a1.y - q1.y) + (a2.y - q2.y);
            d.z = (a0.z - q0.z) + (a1.z - q1.z) + (a2.z - q2.z);
            d.w = (a0.w - q0.w) + (a1.w - q1.w) + (a2.w - q2.w);
        }
        *(float4*)&drow[rg][4 + col0] = d;

        // prefetch next chunk (latency hidden behind both smem phases)
        const int nidx = idx + RGROUPS;
        const int nr   = h0 - 3 + nidx;
        valid = (nidx < ROWSIN) && (nr >= 0) && (nr < HDIM);
        if (valid) {
            const float* xp = xb + (size_t)nr * WDIM + col0;
            const float* yp = yb + (size_t)nr * WDIM + col0;
            a0 = *(const float4*)(xp);
            a1 = *(const float4*)(xp + plane);
            a2 = *(const float4*)(xp + 2 * plane);
            q0 = *(const float4*)(yp);
            q1 = *(const float4*)(yp + plane);
            q2 = *(const float4*)(yp + 2 * plane);
        }

        rg_barrier(rg);                 // drow ready within this row-group

        // horizontal 7-tap sums for 4 columns via 3 aligned LDS.128
        float f[12];
        *(float4*)&f[0] = *(const float4*)&drow[rg][col0];
        *(float4*)&f[4] = *(const float4*)&drow[rg][col0 + 4];
        *(float4*)&f[8] = *(const float4*)&drow[rg][col0 + 8];
        const float s0 = ((f[1] + f[2]) + (f[3] + f[4])) + ((f[5] + f[6]) + f[7]);
        const float s1 = s0 - f[1] + f[8];
        const float s2 = s1 - f[2] + f[9];
        const float s3 = s2 - f[3] + f[10];
        *(float4*)&hs[idx & 15][col0] = make_float4(s0, s1, s2, s3);

        __syncthreads();                // hs rows from all row-groups visible
                                        // (ring WAR safe: next-chunk writes hit slots
                                        //  disjoint from this chunk's reads, mod 16)

        // vertical 7-tap + Charbonnier for output row o = idx - 6
        const int o = idx - 6;
        if (o >= 0 && o < RSTRIP) {
            float4 v = *(const float4*)&hs[o & 15][col0];
            #pragma unroll
            for (int t = 1; t < 7; ++t) {
                const float4 hv = *(const float4*)&hs[(o + t) & 15][col0];
                v.x += hv.x; v.y += hv.y; v.z += hv.z; v.w += hv.w;
            }
            const float inv = 1.f / 49.f;
            v.x *= inv; v.y *= inv; v.z *= inv; v.w *= inv;
            acc += (sqrtf(v.x * v.x + EPSV) + sqrtf(v.y * v.y + EPSV))
                 + (sqrtf(v.z * v.z + EPSV) + sqrtf(v.w * v.w + EPSV));
        }
    }

    // block reduction
    #pragma unroll
    for (int off = 16; off; off >>= 1) acc += __shfl_xor_sync(0xffffffffu, acc, off);
    if ((tid & 31) == 0) warpsum[tid >> 5] = acc;
    __syncthreads();
    if (tid < 32) {
        float v = (tid < THREADS / 32) ? warpsum[tid] : 0.f;
        #pragma unroll
        for (int off = 8; off; off >>= 1) v += __shfl_xor_sync(0xffffffffu, v, off);
        if (tid == 0) {
            g_partials[blk] = v;
            __threadfence();
            const unsigned int t = atomicAdd(&g_count, 1u);
            isLast = (t == NBLOCKS - 1);
        }
    }
    __syncthreads();

    // last-arriving block folds the 256 partials -> scalar (deterministic order)
    if (isLast) {
        __threadfence();
        float v = (tid < NBLOCKS) ? g_partials[tid] : 0.f;
        #pragma unroll
        for (int off = 16; off; off >>= 1) v += __shfl_xor_sync(0xffffffffu, v, off);
        if ((tid & 31) == 0) warpsum[tid >> 5] = v;
        __syncthreads();
        if (tid < 32) {
            float v2 = (tid < THREADS / 32) ? warpsum[tid] : 0.f;
            #pragma unroll
            for (int off = 8; off; off >>= 1) v2 += __shfl_xor_sync(0xffffffffu, v2, off);
            if (tid == 0) {
                out[0]  = v2 / (float)((size_t)BATCH * HDIM * WDIM);
                g_count = 0u;
            }
        }
    }
}

extern "C" void kernel_launch(void* const* d_in, const int* in_sizes, int n_in,
                              void* d_out, int out_size)
{
    (void)in_sizes; (void)n_in; (void)out_size;
    const float* x = (const float*)d_in[0];
    const float* y = (const float*)d_in[1];
    float* out = (float*)d_out;

    charb_kernel<<<NBLOCKS, THREADS>>>(x, y, out);
}